// round 14
// baseline (speedup 1.0000x reference)
#include <cuda_runtime.h>
#include <cstdint>

// Problem dims (fixed by the reference)
static constexpr int Bb  = 2;
static constexpr int Tt  = 2048;
static constexpr int Cc  = 768;
static constexpr int NH  = 12;
static constexpr int HD  = 64;
static constexpr int C3  = 3 * Cc;   // 2304
static constexpr int MM  = Bb * Tt;  // 4096 rows
static constexpr int KK  = Cc;       // 768

// Scratch (allocation-free rule: __device__ globals)
__device__ __align__(16) float g_qkv[(size_t)Bb * Tt * C3];   // [b,t,3c]
__device__ __align__(16) float g_att[(size_t)Bb * Tt * Cc];   // [b,t,c]

// ---------------------------------------------------------------------------
// mma helpers
// ---------------------------------------------------------------------------
__device__ __forceinline__ uint32_t to_tf32(float v) {
    uint32_t r;
    asm("cvt.rna.tf32.f32 %0, %1;" : "=r"(r) : "f"(v));
    return r;
}
__device__ __forceinline__ uint4 to_tf32x4(float4 v) {
    return make_uint4(to_tf32(v.x), to_tf32(v.y), to_tf32(v.z), to_tf32(v.w));
}
__device__ __forceinline__ void mma_tf32(float c[4], uint32_t a0, uint32_t a1, uint32_t a2,
                                         uint32_t a3, uint32_t b0, uint32_t b1) {
    asm volatile(
        "mma.sync.aligned.m16n8k8.row.col.f32.tf32.tf32.f32 "
        "{%0,%1,%2,%3}, {%4,%5,%6,%7}, {%8,%9}, {%0,%1,%2,%3};"
        : "+f"(c[0]), "+f"(c[1]), "+f"(c[2]), "+f"(c[3])
        : "r"(a0), "r"(a1), "r"(a2), "r"(a3), "r"(b0), "r"(b1));
}

// ---------------------------------------------------------------------------
// tf32 mma.sync GEMM, B read DIRECTLY from row-major W[K, N].
// C[M,N] = A[M,768] @ W[768,N]. Smem holds tf32 BITS (cvt on store).
// ---------------------------------------------------------------------------
static constexpr int BM = 128, BN = 128, BK = 32;
static constexpr int NCH  = KK / BK;   // 24
static constexpr int LDA  = 36;
static constexpr int LDB  = 136;
static constexpr int SMA  = BM * LDA;
static constexpr int SMB  = BK * LDB;
static constexpr int GSMQ = (SMA + SMB) * 4;  // 35840 bytes

template <int NTOT>
__device__ __forceinline__ void mmagemm_body(const float* __restrict__ A,
                                             const float* __restrict__ W,
                                             float* __restrict__ C) {
    extern __shared__ uint32_t smu[];
    uint32_t* As = smu;         // [BM][LDA] tf32 bits
    uint32_t* Bs = smu + SMA;   // [BK][LDB] tf32 bits

    const int tid  = threadIdx.x;
    const int lane = tid & 31;
    const int wid  = tid >> 5;
    const int wm   = wid & 1;
    const int wn   = wid >> 1;
    const int lm   = lane >> 2;
    const int lk   = lane & 3;

    const int row0 = blockIdx.y * BM;
    const int col0 = blockIdx.x * BN;
    const float* Ag = A + (size_t)row0 * KK;

    const int lrA = tid >> 3;
    const int lqA = tid & 7;
    const int lrB = tid >> 5;
    const int lqB = tid & 31;

    float acc[4][4][4];
#pragma unroll
    for (int i = 0; i < 4; i++)
#pragma unroll
        for (int j = 0; j < 4; j++)
#pragma unroll
            for (int r = 0; r < 4; r++) acc[i][j][r] = 0.f;

    float4 pa[4], pb[4];
#pragma unroll
    for (int t = 0; t < 4; t++) {
        pa[t] = *(const float4*)(Ag + (size_t)(lrA + t * 32) * KK + lqA * 4);
        pb[t] = *(const float4*)(W + (size_t)(lrB + t * 8) * NTOT + col0 + lqB * 4);
    }

    for (int ch = 0; ch < NCH; ch++) {
#pragma unroll
        for (int t = 0; t < 4; t++) {
            *(uint4*)(As + (lrA + t * 32) * LDA + lqA * 4) = to_tf32x4(pa[t]);
            *(uint4*)(Bs + (lrB + t * 8) * LDB + lqB * 4) = to_tf32x4(pb[t]);
        }
        __syncthreads();

        if (ch + 1 < NCH) {
            const int k1 = (ch + 1) * BK;
#pragma unroll
            for (int t = 0; t < 4; t++) {
                pa[t] = *(const float4*)(Ag + (size_t)(lrA + t * 32) * KK + k1 + lqA * 4);
                pb[t] = *(const float4*)(W + (size_t)(k1 + lrB + t * 8) * NTOT + col0 + lqB * 4);
            }
        }

#pragma unroll
        for (int ks = 0; ks < 4; ks++) {
            const int kb = ks * 8 + lk;
            uint32_t af[4][4], bf[4][2];
#pragma unroll
            for (int i = 0; i < 4; i++) {
                int m0 = wm * 64 + i * 16 + lm;
                af[i][0] = As[m0 * LDA + kb];
                af[i][1] = As[(m0 + 8) * LDA + kb];
                af[i][2] = As[m0 * LDA + kb + 4];
                af[i][3] = As[(m0 + 8) * LDA + kb + 4];
            }
#pragma unroll
            for (int j = 0; j < 4; j++) {
                int n0 = wn * 32 + j * 8 + lm;
                bf[j][0] = Bs[kb * LDB + n0];
                bf[j][1] = Bs[(kb + 4) * LDB + n0];
            }
#pragma unroll
            for (int i = 0; i < 4; i++)
#pragma unroll
                for (int j = 0; j < 4; j++)
                    mma_tf32(acc[i][j], af[i][0], af[i][1], af[i][2], af[i][3],
                             bf[j][0], bf[j][1]);
        }
        __syncthreads();
    }

#pragma unroll
    for (int i = 0; i < 4; i++) {
#pragma unroll
        for (int j = 0; j < 4; j++) {
            int row = row0 + wm * 64 + i * 16 + lm;
            int col = col0 + wn * 32 + j * 8 + 2 * lk;
            float2 v0 = {acc[i][j][0], acc[i][j][1]};
            float2 v1 = {acc[i][j][2], acc[i][j][3]};
            *(float2*)(C + (size_t)row * NTOT + col)       = v0;
            *(float2*)(C + (size_t)(row + 8) * NTOT + col) = v1;
        }
    }
}

__global__ __launch_bounds__(256) void k_mmagemm_qkv(const float* __restrict__ x,
                                                     const float* __restrict__ Wqkv) {
    mmagemm_body<C3>(x, Wqkv, g_qkv);
}
__global__ __launch_bounds__(256) void k_mmagemm_proj(const float* __restrict__ Wproj,
                                                      float* __restrict__ out) {
    mmagemm_body<Cc>(g_att, Wproj, out);
}

// ---------------------------------------------------------------------------
// Causal flash attention, tf32 mma.sync.
// Grid (T/64, NH, B), 128 threads = 4 warps, 16 Q rows/warp.
// Smem holds tf32 bits; Q fragments hoisted out of the K-tile loop;
// Ps aliases Qs (dead after hoist). Smem 53,248 B -> 4 CTAs/SM.
// ---------------------------------------------------------------------------
static constexpr int LQ = 68, LK2 = 68, LV = 72;
static constexpr int SMEM_ATTN2 = (64 * (LQ + LK2 + LV)) * (int)sizeof(uint32_t);  // 53248

__global__ __launch_bounds__(128) void k_attn_mma() {
    extern __shared__ uint32_t smu[];
    uint32_t* Qs = smu;              // [64][LQ] tf32 bits (becomes Ps)
    uint32_t* Ks = Qs + 64 * LQ;     // [64][LK2]
    uint32_t* Vs = Ks + 64 * LK2;    // [64][LV]
    uint32_t* Ps = Qs;               // alias: Qs dead after fragment hoist

    const int b    = blockIdx.z;
    const int h    = blockIdx.y;
    const int q0   = blockIdx.x * 64;
    const int tid  = threadIdx.x;
    const int warp = tid >> 5;
    const int lane = tid & 31;
    const int g    = lane >> 2;
    const int t    = lane & 3;
    const int m0   = warp * 16;
    const size_t base = (size_t)b * Tt * C3;

    // Load Q tile [64][64] -> tf32 bits
#pragma unroll
    for (int u = 0; u < 8; u++) {
        int i  = tid + u * 128;
        int r  = i >> 4;
        int d4 = (i & 15) << 2;
        float4 q = *(const float4*)&g_qkv[base + (size_t)(q0 + r) * C3 + h * HD + d4];
        *(uint4*)&Qs[r * LQ + d4] = to_tf32x4(q);
    }
    __syncthreads();

    // Hoist Q A-fragments (loop-invariant across K tiles).
    uint32_t qf[8][4];
#pragma unroll
    for (int ks = 0; ks < 8; ks++) {
        const int kb = ks * 8 + t;
        qf[ks][0] = Qs[(m0 + g) * LQ + kb];
        qf[ks][1] = Qs[(m0 + g + 8) * LQ + kb];
        qf[ks][2] = Qs[(m0 + g) * LQ + kb + 4];
        qf[ks][3] = Qs[(m0 + g + 8) * LQ + kb + 4];
    }
    // No barrier needed before Ps writes: every warp's hoist precedes the
    // kt-loop barrier; all Ps writes follow it.

    float oa[8][4];
#pragma unroll
    for (int j = 0; j < 8; j++)
#pragma unroll
        for (int r = 0; r < 4; r++) oa[j][r] = 0.f;
    float mrow0 = -1e30f, mrow1 = -1e30f, lrow0 = 0.f, lrow1 = 0.f;

    const int ntiles = (q0 >> 6) + 1;  // causal

    for (int kt = 0; kt < ntiles; kt++) {
        const int k0 = kt * 64;
#pragma unroll
        for (int u = 0; u < 8; u++) {
            int i  = tid + u * 128;
            int r  = i >> 4;
            int d4 = (i & 15) << 2;
            const float* src = &g_qkv[base + (size_t)(k0 + r) * C3 + Cc + h * HD + d4];
            float4 kv = *(const float4*)src;
            float4 vv = *(const float4*)(src + Cc);
            *(uint4*)&Ks[r * LK2 + d4] = to_tf32x4(kv);
            *(uint4*)&Vs[r * LV + d4]  = to_tf32x4(vv);
        }
        __syncthreads();

        // ---- S = Q K^T ----
        float sa[8][4];
#pragma unroll
        for (int j = 0; j < 8; j++)
#pragma unroll
            for (int r = 0; r < 4; r++) sa[j][r] = 0.f;

#pragma unroll
        for (int ks = 0; ks < 8; ks++) {
            const int kb = ks * 8 + t;
#pragma unroll
            for (int j = 0; j < 8; j++) {
                uint32_t b0 = Ks[(j * 8 + g) * LK2 + kb];
                uint32_t b1 = Ks[(j * 8 + g) * LK2 + kb + 4];
                mma_tf32(sa[j], qf[ks][0], qf[ks][1], qf[ks][2], qf[ks][3], b0, b1);
            }
        }

        // ---- scale + causal mask + online softmax ----
        const bool diag = (k0 == q0);
        const int r0 = m0 + g, r1 = r0 + 8;
        float mx0 = -1e30f, mx1 = -1e30f;
#pragma unroll
        for (int j = 0; j < 8; j++) {
            const int c0 = j * 8 + 2 * t, c1 = c0 + 1;
            sa[j][0] *= 0.125f; sa[j][1] *= 0.125f;
            sa[j][2] *= 0.125f; sa[j][3] *= 0.125f;
            if (diag) {
                if (c0 > r0) sa[j][0] = -1e30f;
                if (c1 > r0) sa[j][1] = -1e30f;
                if (c0 > r1) sa[j][2] = -1e30f;
                if (c1 > r1) sa[j][3] = -1e30f;
            }
            mx0 = fmaxf(mx0, fmaxf(sa[j][0], sa[j][1]));
            mx1 = fmaxf(mx1, fmaxf(sa[j][2], sa[j][3]));
        }
#pragma unroll
        for (int off = 1; off <= 2; off <<= 1) {
            mx0 = fmaxf(mx0, __shfl_xor_sync(0xffffffffu, mx0, off));
            mx1 = fmaxf(mx1, __shfl_xor_sync(0xffffffffu, mx1, off));
        }
        const float mn0 = fmaxf(mrow0, mx0);
        const float mn1 = fmaxf(mrow1, mx1);
        const float scl0 = __expf(mrow0 - mn0);
        const float scl1 = __expf(mrow1 - mn1);
        mrow0 = mn0; mrow1 = mn1;

        float sum0 = 0.f, sum1 = 0.f;
#pragma unroll
        for (int j = 0; j < 8; j++) {
            const int c0 = j * 8 + 2 * t;
            float p00 = __expf(sa[j][0] - mn0);
            float p01 = __expf(sa[j][1] - mn0);
            float p10 = __expf(sa[j][2] - mn1);
            float p11 = __expf(sa[j][3] - mn1);
            sum0 += p00 + p01;
            sum1 += p10 + p11;
            *(uint2*)&Ps[r0 * LQ + c0] = make_uint2(to_tf32(p00), to_tf32(p01));
            *(uint2*)&Ps[r1 * LQ + c0] = make_uint2(to_tf32(p10), to_tf32(p11));
        }
#pragma unroll
        for (int off = 1; off <= 2; off <<= 1) {
            sum0 += __shfl_xor_sync(0xffffffffu, sum0, off);
            sum1 += __shfl_xor_sync(0xffffffffu, sum1, off);
        }
        lrow0 = lrow0 * scl0 + sum0;
        lrow1 = lrow1 * scl1 + sum1;
#pragma unroll
        for (int j = 0; j < 8; j++) {
            oa[j][0] *= scl0; oa[j][1] *= scl0;
            oa[j][2] *= scl1; oa[j][3] *= scl1;
        }
        __syncwarp();  // this warp's Ps rows written by this warp only

        // ---- O += P V ----
#pragma unroll
        for (int kc = 0; kc < 8; kc++) {
            const int kb = kc * 8 + t;
            uint32_t a0 = Ps[(m0 + g) * LQ + kb];
            uint32_t a1 = Ps[(m0 + g + 8) * LQ + kb];
            uint32_t a2 = Ps[(m0 + g) * LQ + kb + 4];
            uint32_t a3 = Ps[(m0 + g + 8) * LQ + kb + 4];
#pragma unroll
            for (int j = 0; j < 8; j++) {
                uint32_t b0 = Vs[kb * LV + j * 8 + g];
                uint32_t b1 = Vs[(kb + 4) * LV + j * 8 + g];
                mma_tf32(oa[j], a0, a1, a2, a3, b0, b1);
            }
        }
        __syncthreads();  // protect Ks/Vs before next tile
    }

    // ---- normalize + write out ([b,t,c] layout, transpose folded) ----
    const float inv0 = 1.f / lrow0;
    const float inv1 = 1.f / lrow1;
    const int gr0 = q0 + m0 + g, gr1 = gr0 + 8;
#pragma unroll
    for (int j = 0; j < 8; j++) {
        const int col = h * HD + j * 8 + 2 * t;
        *(float2*)&g_att[(size_t)(b * Tt + gr0) * Cc + col] =
            make_float2(oa[j][0] * inv0, oa[j][1] * inv0);
        *(float2*)&g_att[(size_t)(b * Tt + gr1) * Cc + col] =
            make_float2(oa[j][2] * inv1, oa[j][3] * inv1);
    }
}

// ---------------------------------------------------------------------------
// Launch: qkv GEMM (mma) -> attention (mma) -> proj GEMM (mma)
// Inputs (metadata order): x, mask (ignored; causality analytic), Wqkv, Wproj
// ---------------------------------------------------------------------------
extern "C" void kernel_launch(void* const* d_in, const int* in_sizes, int n_in,
                              void* d_out, int out_size) {
    (void)in_sizes; (void)n_in; (void)out_size;
    const float* x     = (const float*)d_in[0];
    const float* Wqkv  = (const float*)d_in[2];
    const float* Wproj = (const float*)d_in[3];
    float* out = (float*)d_out;

    cudaFuncSetAttribute(k_attn_mma, cudaFuncAttributeMaxDynamicSharedMemorySize, SMEM_ATTN2);

    k_mmagemm_qkv<<<dim3(C3 / BN, MM / BM), 256, GSMQ>>>(x, Wqkv);
    k_attn_mma<<<dim3(Tt / 64, NH, Bb), 128, SMEM_ATTN2>>>();
    k_mmagemm_proj<<<dim3(Cc / BN, MM / BM), 256, GSMQ>>>(Wproj, out);
}

// round 15
// speedup vs baseline: 1.5040x; 1.5040x over previous
#include <cuda_runtime.h>
#include <cstdint>

// Problem dims (fixed by the reference)
static constexpr int Bb  = 2;
static constexpr int Tt  = 2048;
static constexpr int Cc  = 768;
static constexpr int NH  = 12;
static constexpr int HD  = 64;
static constexpr int C3  = 3 * Cc;   // 2304
static constexpr int MM  = Bb * Tt;  // 4096 rows
static constexpr int KK  = Cc;       // 768

// Scratch (allocation-free rule: __device__ globals)
__device__ __align__(16) float g_qkv[(size_t)Bb * Tt * C3];   // [b,t,3c]
__device__ __align__(16) float g_att[(size_t)Bb * Tt * Cc];   // [b,t,c]

// ---------------------------------------------------------------------------
// mma helpers
// ---------------------------------------------------------------------------
__device__ __forceinline__ uint32_t to_tf32(float v) {
    uint32_t r;
    asm("cvt.rna.tf32.f32 %0, %1;" : "=r"(r) : "f"(v));
    return r;
}
__device__ __forceinline__ void mma_tf32(float c[4], uint32_t a0, uint32_t a1, uint32_t a2,
                                         uint32_t a3, uint32_t b0, uint32_t b1) {
    asm volatile(
        "mma.sync.aligned.m16n8k8.row.col.f32.tf32.tf32.f32 "
        "{%0,%1,%2,%3}, {%4,%5,%6,%7}, {%8,%9}, {%0,%1,%2,%3};"
        : "+f"(c[0]), "+f"(c[1]), "+f"(c[2]), "+f"(c[3])
        : "r"(a0), "r"(a1), "r"(a2), "r"(a3), "r"(b0), "r"(b1));
}

// ---------------------------------------------------------------------------
// tf32 mma.sync GEMM, B read DIRECTLY from row-major W[K, N].
// C[M,N] = A[M,768] @ W[768,N]. (Byte-identical to the round-13 version:
// float smem, cvt in the inner loop — measured 101.6us on qkv.)
// ---------------------------------------------------------------------------
static constexpr int BM = 128, BN = 128, BK = 32;
static constexpr int NCH  = KK / BK;   // 24
static constexpr int LDA  = 36;
static constexpr int LDB  = 136;
static constexpr int SMA  = BM * LDA;
static constexpr int SMB  = BK * LDB;
static constexpr int GSMQ = (SMA + SMB) * 4;  // 35840 bytes

template <int NTOT>
__device__ __forceinline__ void mmagemm_body(const float* __restrict__ A,
                                             const float* __restrict__ W,
                                             float* __restrict__ C) {
    extern __shared__ float sm[];
    float* As = sm;         // [BM][LDA]
    float* Bs = sm + SMA;   // [BK][LDB]

    const int tid  = threadIdx.x;
    const int lane = tid & 31;
    const int wid  = tid >> 5;
    const int wm   = wid & 1;
    const int wn   = wid >> 1;
    const int lm   = lane >> 2;
    const int lk   = lane & 3;

    const int row0 = blockIdx.y * BM;
    const int col0 = blockIdx.x * BN;
    const float* Ag = A + (size_t)row0 * KK;

    const int lrA = tid >> 3;
    const int lqA = tid & 7;
    const int lrB = tid >> 5;
    const int lqB = tid & 31;

    float acc[4][4][4];
#pragma unroll
    for (int i = 0; i < 4; i++)
#pragma unroll
        for (int j = 0; j < 4; j++)
#pragma unroll
            for (int r = 0; r < 4; r++) acc[i][j][r] = 0.f;

    float4 pa[4], pb[4];
#pragma unroll
    for (int t = 0; t < 4; t++) {
        pa[t] = *(const float4*)(Ag + (size_t)(lrA + t * 32) * KK + lqA * 4);
        pb[t] = *(const float4*)(W + (size_t)(lrB + t * 8) * NTOT + col0 + lqB * 4);
    }

    for (int ch = 0; ch < NCH; ch++) {
#pragma unroll
        for (int t = 0; t < 4; t++) {
            *(float4*)(As + (lrA + t * 32) * LDA + lqA * 4) = pa[t];
            *(float4*)(Bs + (lrB + t * 8) * LDB + lqB * 4) = pb[t];
        }
        __syncthreads();

        if (ch + 1 < NCH) {
            const int k1 = (ch + 1) * BK;
#pragma unroll
            for (int t = 0; t < 4; t++) {
                pa[t] = *(const float4*)(Ag + (size_t)(lrA + t * 32) * KK + k1 + lqA * 4);
                pb[t] = *(const float4*)(W + (size_t)(k1 + lrB + t * 8) * NTOT + col0 + lqB * 4);
            }
        }

#pragma unroll
        for (int ks = 0; ks < 4; ks++) {
            const int kb = ks * 8 + lk;
            uint32_t af[4][4], bf[4][2];
#pragma unroll
            for (int i = 0; i < 4; i++) {
                int m0 = wm * 64 + i * 16 + lm;
                af[i][0] = to_tf32(As[m0 * LDA + kb]);
                af[i][1] = to_tf32(As[(m0 + 8) * LDA + kb]);
                af[i][2] = to_tf32(As[m0 * LDA + kb + 4]);
                af[i][3] = to_tf32(As[(m0 + 8) * LDA + kb + 4]);
            }
#pragma unroll
            for (int j = 0; j < 4; j++) {
                int n0 = wn * 32 + j * 8 + lm;
                bf[j][0] = to_tf32(Bs[kb * LDB + n0]);
                bf[j][1] = to_tf32(Bs[(kb + 4) * LDB + n0]);
            }
#pragma unroll
            for (int i = 0; i < 4; i++)
#pragma unroll
                for (int j = 0; j < 4; j++)
                    mma_tf32(acc[i][j], af[i][0], af[i][1], af[i][2], af[i][3],
                             bf[j][0], bf[j][1]);
        }
        __syncthreads();
    }

#pragma unroll
    for (int i = 0; i < 4; i++) {
#pragma unroll
        for (int j = 0; j < 4; j++) {
            int row = row0 + wm * 64 + i * 16 + lm;
            int col = col0 + wn * 32 + j * 8 + 2 * lk;
            float2 v0 = {acc[i][j][0], acc[i][j][1]};
            float2 v1 = {acc[i][j][2], acc[i][j][3]};
            *(float2*)(C + (size_t)row * NTOT + col)       = v0;
            *(float2*)(C + (size_t)(row + 8) * NTOT + col) = v1;
        }
    }
}

__global__ __launch_bounds__(256) void k_mmagemm_qkv(const float* __restrict__ x,
                                                     const float* __restrict__ Wqkv) {
    mmagemm_body<C3>(x, Wqkv, g_qkv);
}
__global__ __launch_bounds__(256) void k_mmagemm_proj(const float* __restrict__ Wproj,
                                                      float* __restrict__ out) {
    mmagemm_body<Cc>(g_att, Wproj, out);
}

// ---------------------------------------------------------------------------
// Causal flash attention, tf32 mma.sync.
// Round-13 base (float smem, cvt in loop) + Q-fragment hoist + Ps aliases Qs.
// Grid (T/64, NH, B), 128 threads = 4 warps, 16 Q rows/warp.
// Smem 53,248 B -> 4 CTAs/SM.
// ---------------------------------------------------------------------------
static constexpr int LQ = 68, LK2 = 68, LV = 72;
static constexpr int SMEM_ATTN2 = (64 * (LQ + LK2 + LV)) * (int)sizeof(float);  // 53248

__global__ __launch_bounds__(128) void k_attn_mma() {
    extern __shared__ float sm[];
    float* Qs = sm;                  // [64][LQ] (becomes Ps after hoist)
    float* Ks = Qs + 64 * LQ;        // [64][LK2]
    float* Vs = Ks + 64 * LK2;       // [64][LV]
    float* Ps = Qs;                  // alias: Qs dead after fragment hoist

    const int b    = blockIdx.z;
    const int h    = blockIdx.y;
    const int q0   = blockIdx.x * 64;
    const int tid  = threadIdx.x;
    const int warp = tid >> 5;
    const int lane = tid & 31;
    const int g    = lane >> 2;
    const int t    = lane & 3;
    const int m0   = warp * 16;
    const size_t base = (size_t)b * Tt * C3;

    // Load Q tile [64][64]
#pragma unroll
    for (int u = 0; u < 8; u++) {
        int i  = tid + u * 128;
        int r  = i >> 4;
        int d4 = (i & 15) << 2;
        *(float4*)&Qs[r * LQ + d4] =
            *(const float4*)&g_qkv[base + (size_t)(q0 + r) * C3 + h * HD + d4];
    }
    __syncthreads();

    // Hoist Q A-fragments (loop-invariant across K tiles; cvt once here).
    // Warp w reads only rows m0..m0+15, the same rows it later overwrites via
    // Ps — per-warp ownership, so no barrier needed before Ps writes.
    uint32_t qf[8][4];
#pragma unroll
    for (int ks = 0; ks < 8; ks++) {
        const int kb = ks * 8 + t;
        qf[ks][0] = to_tf32(Qs[(m0 + g) * LQ + kb]);
        qf[ks][1] = to_tf32(Qs[(m0 + g + 8) * LQ + kb]);
        qf[ks][2] = to_tf32(Qs[(m0 + g) * LQ + kb + 4]);
        qf[ks][3] = to_tf32(Qs[(m0 + g + 8) * LQ + kb + 4]);
    }

    float oa[8][4];
#pragma unroll
    for (int j = 0; j < 8; j++)
#pragma unroll
        for (int r = 0; r < 4; r++) oa[j][r] = 0.f;
    float mrow0 = -1e30f, mrow1 = -1e30f, lrow0 = 0.f, lrow1 = 0.f;

    const int ntiles = (q0 >> 6) + 1;  // causal

    for (int kt = 0; kt < ntiles; kt++) {
        const int k0 = kt * 64;
#pragma unroll
        for (int u = 0; u < 8; u++) {
            int i  = tid + u * 128;
            int r  = i >> 4;
            int d4 = (i & 15) << 2;
            const float* src = &g_qkv[base + (size_t)(k0 + r) * C3 + Cc + h * HD + d4];
            *(float4*)&Ks[r * LK2 + d4] = *(const float4*)src;
            *(float4*)&Vs[r * LV + d4]  = *(const float4*)(src + Cc);
        }
        __syncthreads();

        // ---- S = Q K^T ----
        float sa[8][4];
#pragma unroll
        for (int j = 0; j < 8; j++)
#pragma unroll
            for (int r = 0; r < 4; r++) sa[j][r] = 0.f;

#pragma unroll
        for (int ks = 0; ks < 8; ks++) {
            const int kb = ks * 8 + t;
#pragma unroll
            for (int j = 0; j < 8; j++) {
                uint32_t b0 = to_tf32(Ks[(j * 8 + g) * LK2 + kb]);
                uint32_t b1 = to_tf32(Ks[(j * 8 + g) * LK2 + kb + 4]);
                mma_tf32(sa[j], qf[ks][0], qf[ks][1], qf[ks][2], qf[ks][3], b0, b1);
            }
        }

        // ---- scale + causal mask + online softmax ----
        const bool diag = (k0 == q0);
        const int r0 = m0 + g, r1 = r0 + 8;
        float mx0 = -1e30f, mx1 = -1e30f;
#pragma unroll
        for (int j = 0; j < 8; j++) {
            const int c0 = j * 8 + 2 * t, c1 = c0 + 1;
            sa[j][0] *= 0.125f; sa[j][1] *= 0.125f;
            sa[j][2] *= 0.125f; sa[j][3] *= 0.125f;
            if (diag) {
                if (c0 > r0) sa[j][0] = -1e30f;
                if (c1 > r0) sa[j][1] = -1e30f;
                if (c0 > r1) sa[j][2] = -1e30f;
                if (c1 > r1) sa[j][3] = -1e30f;
            }
            mx0 = fmaxf(mx0, fmaxf(sa[j][0], sa[j][1]));
            mx1 = fmaxf(mx1, fmaxf(sa[j][2], sa[j][3]));
        }
#pragma unroll
        for (int off = 1; off <= 2; off <<= 1) {
            mx0 = fmaxf(mx0, __shfl_xor_sync(0xffffffffu, mx0, off));
            mx1 = fmaxf(mx1, __shfl_xor_sync(0xffffffffu, mx1, off));
        }
        const float mn0 = fmaxf(mrow0, mx0);
        const float mn1 = fmaxf(mrow1, mx1);
        const float scl0 = __expf(mrow0 - mn0);
        const float scl1 = __expf(mrow1 - mn1);
        mrow0 = mn0; mrow1 = mn1;

        float sum0 = 0.f, sum1 = 0.f;
#pragma unroll
        for (int j = 0; j < 8; j++) {
            const int c0 = j * 8 + 2 * t;
            float p00 = __expf(sa[j][0] - mn0);
            float p01 = __expf(sa[j][1] - mn0);
            float p10 = __expf(sa[j][2] - mn1);
            float p11 = __expf(sa[j][3] - mn1);
            sum0 += p00 + p01;
            sum1 += p10 + p11;
            *(float2*)&Ps[r0 * LQ + c0] = make_float2(p00, p01);
            *(float2*)&Ps[r1 * LQ + c0] = make_float2(p10, p11);
        }
#pragma unroll
        for (int off = 1; off <= 2; off <<= 1) {
            sum0 += __shfl_xor_sync(0xffffffffu, sum0, off);
            sum1 += __shfl_xor_sync(0xffffffffu, sum1, off);
        }
        lrow0 = lrow0 * scl0 + sum0;
        lrow1 = lrow1 * scl1 + sum1;
#pragma unroll
        for (int j = 0; j < 8; j++) {
            oa[j][0] *= scl0; oa[j][1] *= scl0;
            oa[j][2] *= scl1; oa[j][3] *= scl1;
        }
        __syncwarp();  // this warp's Ps rows written by this warp only

        // ---- O += P V ----
#pragma unroll
        for (int kc = 0; kc < 8; kc++) {
            const int kb = kc * 8 + t;
            uint32_t a0 = to_tf32(Ps[(m0 + g) * LQ + kb]);
            uint32_t a1 = to_tf32(Ps[(m0 + g + 8) * LQ + kb]);
            uint32_t a2 = to_tf32(Ps[(m0 + g) * LQ + kb + 4]);
            uint32_t a3 = to_tf32(Ps[(m0 + g + 8) * LQ + kb + 4]);
#pragma unroll
            for (int j = 0; j < 8; j++) {
                uint32_t b0 = to_tf32(Vs[kb * LV + j * 8 + g]);
                uint32_t b1 = to_tf32(Vs[(kb + 4) * LV + j * 8 + g]);
                mma_tf32(oa[j], a0, a1, a2, a3, b0, b1);
            }
        }
        __syncthreads();  // protect Ks/Vs before next tile
    }

    // ---- normalize + write out ([b,t,c] layout, transpose folded) ----
    const float inv0 = 1.f / lrow0;
    const float inv1 = 1.f / lrow1;
    const int gr0 = q0 + m0 + g, gr1 = gr0 + 8;
#pragma unroll
    for (int j = 0; j < 8; j++) {
        const int col = h * HD + j * 8 + 2 * t;
        *(float2*)&g_att[(size_t)(b * Tt + gr0) * Cc + col] =
            make_float2(oa[j][0] * inv0, oa[j][1] * inv0);
        *(float2*)&g_att[(size_t)(b * Tt + gr1) * Cc + col] =
            make_float2(oa[j][2] * inv1, oa[j][3] * inv1);
    }
}

// ---------------------------------------------------------------------------
// Launch: qkv GEMM (mma) -> attention (mma) -> proj GEMM (mma)
// Inputs (metadata order): x, mask (ignored; causality analytic), Wqkv, Wproj
// ---------------------------------------------------------------------------
extern "C" void kernel_launch(void* const* d_in, const int* in_sizes, int n_in,
                              void* d_out, int out_size) {
    (void)in_sizes; (void)n_in; (void)out_size;
    const float* x     = (const float*)d_in[0];
    const float* Wqkv  = (const float*)d_in[2];
    const float* Wproj = (const float*)d_in[3];
    float* out = (float*)d_out;

    cudaFuncSetAttribute(k_attn_mma, cudaFuncAttributeMaxDynamicSharedMemorySize, SMEM_ATTN2);

    k_mmagemm_qkv<<<dim3(C3 / BN, MM / BM), 256, GSMQ>>>(x, Wqkv);
    k_attn_mma<<<dim3(Tt / 64, NH, Bb), 128, SMEM_ATTN2>>>();
    k_mmagemm_proj<<<dim3(Cc / BN, MM / BM), 256, GSMQ>>>(Wproj, out);
}